// round 4
// baseline (speedup 1.0000x reference)
#include <cuda_runtime.h>
#include <math.h>

#define TT 6
#define NN 50000
#define EE 800000
#define FF 32
#define HH 64
#define OUTC 16
#define SPAD 68

// ---------------- scratch (device globals; no allocation allowed) ----------
__device__ __align__(16) float g_aggx[(size_t)TT * NN * FF];   // A_hat@X, all steps (38.4MB)
__device__ __align__(16) float g_P   [(size_t)TT * NN * 192];  // aggx@[Mz|Mr|Mh] (230MB)
__device__ __align__(16) float g_h   [(size_t)NN * HH];
__device__ int   g_deg [TT * NN];
__device__ float g_dinv[TT * NN];

// folded / transposed weights
__device__ __align__(16) float g_Mt [3][HH][FF];  // (W @ L_top)^T
__device__ __align__(16) float g_Lbt[3][HH][HH];  // L_bot^T
__device__ float g_bv[3][HH];

__device__ __forceinline__ float sigmoidf_(float x) {
    return 1.0f / (1.0f + __expf(-x));
}

// ---------------- prep / clears ---------------------------------------------

__global__ void k_clear_h() {
    unsigned idx = blockIdx.x * blockDim.x + threadIdx.x;
    if (idx < (unsigned)(NN * HH)) g_h[idx] = 0.0f;
}

__global__ void k_clear_deg_all() {
    unsigned i = blockIdx.x * blockDim.x + threadIdx.x;
    if (i < (unsigned)(TT * NN)) g_deg[i] = 0;
}

// one block per gate
__global__ void k_prep(const float* __restrict__ Wz, const float* __restrict__ bz,
                       const float* __restrict__ Wr, const float* __restrict__ br,
                       const float* __restrict__ Wh, const float* __restrict__ bh,
                       const float* __restrict__ Lz, const float* __restrict__ Lzb,
                       const float* __restrict__ Lr, const float* __restrict__ Lrb,
                       const float* __restrict__ Lh, const float* __restrict__ Lhb) {
    int g = blockIdx.x;
    int t = threadIdx.x;
    const float* W  = (g == 0) ? Wz  : (g == 1) ? Wr  : Wh;
    const float* b  = (g == 0) ? bz  : (g == 1) ? br  : bh;
    const float* L  = (g == 0) ? Lz  : (g == 1) ? Lr  : Lh;
    const float* Lb = (g == 0) ? Lzb : (g == 1) ? Lrb : Lhb;

    // Mt[g][j][f] = sum_m W[f][m] * L[m][j]  (2048 entries / 256 threads = 8 each)
    for (int e = t; e < HH * FF; e += 256) {
        int j = e >> 5, f = e & 31;
        float s = 0.f;
        #pragma unroll 8
        for (int m = 0; m < HH; m++) s += __ldg(W + f * HH + m) * __ldg(L + m * HH + j);
        g_Mt[g][j][f] = s;
    }
    // Lbt[g][j][k] = L[HH+k][j]
    for (int e = t; e < HH * HH; e += 256) {
        int j = e >> 6, k = e & 63;
        g_Lbt[g][j][k] = __ldg(L + (HH + k) * HH + j);
    }
    if (t < HH) {
        float sb = __ldg(Lb + t);
        #pragma unroll 8
        for (int m = 0; m < HH; m++) sb += __ldg(b + m) * __ldg(L + m * HH + t);
        g_bv[g][t] = sb;
    }
}

// ---------------- batched graph preprocessing (all timesteps) ---------------

#define DEG_BPS  3125          // EE/256
#define INIT_BPS 1563          // ceil(NN*8/256)
#define SCAT_BPS 25000         // EE*8/256

__global__ void k_deg_all(const int* __restrict__ ei) {
    int t = blockIdx.x / DEG_BPS;
    unsigned e = (blockIdx.x % DEG_BPS) * 256 + threadIdx.x;
    int d = __ldg(ei + (size_t)t * 2 * EE + EE + e);
    atomicAdd(&g_deg[t * NN + d], 1);
}

__global__ void k_init_all(const float* __restrict__ xs) {
    int t = blockIdx.x / INIT_BPS;
    unsigned local = (blockIdx.x % INIT_BPS) * 256 + threadIdx.x;
    if (local >= (unsigned)NN * 8u) return;
    unsigned i = local >> 3, c = local & 7u;
    float di = rsqrtf((float)(g_deg[t * NN + i] + 1));
    if (c == 0) g_dinv[t * NN + i] = di;
    float dd = di * di;
    const float* x = xs + (size_t)t * NN * FF;
    float4 v = __ldg(reinterpret_cast<const float4*>(x + (size_t)i * FF) + c);
    v.x *= dd; v.y *= dd; v.z *= dd; v.w *= dd;
    reinterpret_cast<float4*>(g_aggx + ((size_t)t * NN + i) * FF)[c] = v;
}

__global__ void k_scatter_all(const float* __restrict__ xs, const int* __restrict__ ei) {
    int t = blockIdx.x / SCAT_BPS;
    unsigned local = (blockIdx.x % SCAT_BPS) * 256 + threadIdx.x;
    unsigned e = local >> 3;
    unsigned c = local & 7u;
    const int* src = ei + (size_t)t * 2 * EE;
    int s = __ldg(src + e);
    int d = __ldg(src + EE + e);
    float nrm = __ldg(&g_dinv[t * NN + s]) * __ldg(&g_dinv[t * NN + d]);
    const float* x = xs + (size_t)t * NN * FF;
    float4 v = __ldg(reinterpret_cast<const float4*>(x + (size_t)s * FF) + c);
    v.x *= nrm; v.y *= nrm; v.z *= nrm; v.w *= nrm;
    float4* ap = reinterpret_cast<float4*>(g_aggx + ((size_t)t * NN + d) * FF) + c;
    asm volatile("red.global.add.v4.f32 [%0], {%1,%2,%3,%4};"
                 :: "l"(ap), "f"(v.x), "f"(v.y), "f"(v.z), "f"(v.w) : "memory");
}

// ---------------- P = aggx @ [Mz|Mr|Mh]  (300000 x 32 -> 192) ---------------
// block = 256 threads = 8 warps = 64 rows. Warp: 8 rows; lane owns cols lane+32c.
__global__ void __launch_bounds__(256) k_P() {
    __shared__ float ag_sh[FF][SPAD];
    int tid = threadIdx.x;
    size_t row_base = (size_t)blockIdx.x * 64;
    const size_t NROWS = (size_t)TT * NN;

    #pragma unroll
    for (int r = 0; r < 2; r++) {
        int idx = r * 256 + tid;
        int n = idx >> 3, k4 = idx & 7;
        size_t row = row_base + n;
        float4 v = make_float4(0.f, 0.f, 0.f, 0.f);
        if (row < NROWS) v = __ldg(reinterpret_cast<const float4*>(g_aggx + row * FF) + k4);
        ag_sh[k4 * 4 + 0][n] = v.x;
        ag_sh[k4 * 4 + 1][n] = v.y;
        ag_sh[k4 * 4 + 2][n] = v.z;
        ag_sh[k4 * 4 + 3][n] = v.w;
    }
    __syncthreads();

    int warp = tid >> 5, lane = tid & 31;
    int nb = warp * 8;
    const float* Mflat = &g_Mt[0][0][0];   // column j -> row Mflat + j*FF

    float acc[6][8];
    #pragma unroll
    for (int c = 0; c < 6; c++)
        #pragma unroll
        for (int n = 0; n < 8; n++) acc[c][n] = 0.f;

    #pragma unroll
    for (int k4 = 0; k4 < FF / 4; k4++) {
        float4 w[6];
        #pragma unroll
        for (int c = 0; c < 6; c++)
            w[c] = __ldg(reinterpret_cast<const float4*>(Mflat + (c * 32 + lane) * FF) + k4);
        const float* wp = (const float*)&w[0];
        #pragma unroll
        for (int i = 0; i < 4; i++) {
            int k = k4 * 4 + i;
            float4 a0 = *reinterpret_cast<const float4*>(&ag_sh[k][nb]);
            float4 a1 = *reinterpret_cast<const float4*>(&ag_sh[k][nb + 4]);
            float aa[8] = {a0.x, a0.y, a0.z, a0.w, a1.x, a1.y, a1.z, a1.w};
            #pragma unroll
            for (int c = 0; c < 6; c++) {
                float wv = wp[c * 4 + i];
                #pragma unroll
                for (int n = 0; n < 8; n++) acc[c][n] = fmaf(aa[n], wv, acc[c][n]);
            }
        }
    }

    #pragma unroll
    for (int n = 0; n < 8; n++) {
        size_t row = row_base + nb + n;
        if (row < NROWS) {
            float* pr = g_P + row * 192;
            #pragma unroll
            for (int c = 0; c < 6; c++) pr[c * 32 + lane] = acc[c][n];
        }
    }
}

// ---------------- recurrent gates: h' from P_t and h ------------------------
__global__ void __launch_bounds__(256) k_gates3(int t) {
    __shared__ float h_sh [HH][SPAD];
    __shared__ float hr_sh[HH][SPAD];

    int tid = threadIdx.x;
    int block_base = blockIdx.x * 64;

    #pragma unroll
    for (int r = 0; r < 4; r++) {
        int idx = r * 256 + tid;
        int n = idx >> 4, k4 = idx & 15;
        int node = block_base + n;
        float4 v = make_float4(0.f, 0.f, 0.f, 0.f);
        if (node < NN) v = __ldg(reinterpret_cast<const float4*>(g_h + (size_t)node * HH) + k4);
        h_sh[k4 * 4 + 0][n] = v.x;
        h_sh[k4 * 4 + 1][n] = v.y;
        h_sh[k4 * 4 + 2][n] = v.z;
        h_sh[k4 * 4 + 3][n] = v.w;
    }
    __syncthreads();

    int warp = tid >> 5, lane = tid & 31;
    int nb = warp * 8;
    int j0 = lane, j1 = lane + 32;

    // init accumulators from precomputed projections P
    float az0[8], az1[8], ar0[8], ar1[8];
    #pragma unroll
    for (int n = 0; n < 8; n++) {
        int node = block_base + nb + n;
        if (node < NN) {
            const float* pr = g_P + ((size_t)t * NN + node) * 192;
            az0[n] = __ldg(pr + j0);        az1[n] = __ldg(pr + j1);
            ar0[n] = __ldg(pr + 64 + j0);   ar1[n] = __ldg(pr + 64 + j1);
        } else { az0[n] = az1[n] = ar0[n] = ar1[n] = 0.f; }
    }

    // z,r += h @ Lbt
    #pragma unroll
    for (int k4 = 0; k4 < HH / 4; k4++) {
        float4 wz0 = __ldg(reinterpret_cast<const float4*>(&g_Lbt[0][j0][0]) + k4);
        float4 wz1 = __ldg(reinterpret_cast<const float4*>(&g_Lbt[0][j1][0]) + k4);
        float4 wr0 = __ldg(reinterpret_cast<const float4*>(&g_Lbt[1][j0][0]) + k4);
        float4 wr1 = __ldg(reinterpret_cast<const float4*>(&g_Lbt[1][j1][0]) + k4);
        const float* pz0 = (const float*)&wz0; const float* pz1 = (const float*)&wz1;
        const float* pr0 = (const float*)&wr0; const float* pr1 = (const float*)&wr1;
        #pragma unroll
        for (int i = 0; i < 4; i++) {
            int k = k4 * 4 + i;
            float4 a0 = *reinterpret_cast<const float4*>(&h_sh[k][nb]);
            float4 a1 = *reinterpret_cast<const float4*>(&h_sh[k][nb + 4]);
            float aa[8] = {a0.x, a0.y, a0.z, a0.w, a1.x, a1.y, a1.z, a1.w};
            #pragma unroll
            for (int n = 0; n < 8; n++) {
                az0[n] = fmaf(aa[n], pz0[i], az0[n]);
                az1[n] = fmaf(aa[n], pz1[i], az1[n]);
                ar0[n] = fmaf(aa[n], pr0[i], ar0[n]);
                ar1[n] = fmaf(aa[n], pr1[i], ar1[n]);
            }
        }
    }

    float bvz0 = __ldg(&g_bv[0][j0]), bvz1 = __ldg(&g_bv[0][j1]);
    float bvr0 = __ldg(&g_bv[1][j0]), bvr1 = __ldg(&g_bv[1][j1]);

    float Z0a[8], Z1a[8];
    #pragma unroll
    for (int n = 0; n < 8; n++) {
        Z0a[n] = sigmoidf_(az0[n] + bvz0);
        Z1a[n] = sigmoidf_(az1[n] + bvz1);
        float R0 = sigmoidf_(ar0[n] + bvr0);
        float R1 = sigmoidf_(ar1[n] + bvr1);
        hr_sh[j0][nb + n] = h_sh[j0][nb + n] * R0;
        hr_sh[j1][nb + n] = h_sh[j1][nb + n] * R1;
    }
    __syncwarp();

    // h gate
    float ah0[8], ah1[8];
    #pragma unroll
    for (int n = 0; n < 8; n++) {
        int node = block_base + nb + n;
        if (node < NN) {
            const float* pr = g_P + ((size_t)t * NN + node) * 192;
            ah0[n] = __ldg(pr + 128 + j0);
            ah1[n] = __ldg(pr + 128 + j1);
        } else { ah0[n] = ah1[n] = 0.f; }
    }
    #pragma unroll
    for (int k4 = 0; k4 < HH / 4; k4++) {
        float4 wh0 = __ldg(reinterpret_cast<const float4*>(&g_Lbt[2][j0][0]) + k4);
        float4 wh1 = __ldg(reinterpret_cast<const float4*>(&g_Lbt[2][j1][0]) + k4);
        const float* p0 = (const float*)&wh0; const float* p1 = (const float*)&wh1;
        #pragma unroll
        for (int i = 0; i < 4; i++) {
            int k = k4 * 4 + i;
            float4 a0 = *reinterpret_cast<const float4*>(&hr_sh[k][nb]);
            float4 a1 = *reinterpret_cast<const float4*>(&hr_sh[k][nb + 4]);
            float aa[8] = {a0.x, a0.y, a0.z, a0.w, a1.x, a1.y, a1.z, a1.w};
            #pragma unroll
            for (int n = 0; n < 8; n++) {
                ah0[n] = fmaf(aa[n], p0[i], ah0[n]);
                ah1[n] = fmaf(aa[n], p1[i], ah1[n]);
            }
        }
    }

    float bvh0 = __ldg(&g_bv[2][j0]), bvh1 = __ldg(&g_bv[2][j1]);
    #pragma unroll
    for (int n = 0; n < 8; n++) {
        int node = block_base + nb + n;
        if (node < NN) {
            float Ht0 = tanhf(ah0[n] + bvh0);
            float Ht1 = tanhf(ah1[n] + bvh1);
            float h0 = h_sh[j0][nb + n];
            float h1 = h_sh[j1][nb + n];
            g_h[(size_t)node * HH + j0] = Z0a[n] * h0 + (1.f - Z0a[n]) * Ht0;
            g_h[(size_t)node * HH + j1] = Z1a[n] * h1 + (1.f - Z1a[n]) * Ht1;
        }
    }
}

__global__ void k_out(const float* __restrict__ oW, const float* __restrict__ ob,
                      float* __restrict__ out) {
    unsigned idx = blockIdx.x * blockDim.x + threadIdx.x;
    if (idx >= (unsigned)(NN * OUTC)) return;
    int i = idx >> 4, j = idx & 15;
    const float* hr = g_h + (size_t)i * HH;
    float acc = __ldg(ob + j);
    #pragma unroll
    for (int k = 0; k < HH; k++) acc += hr[k] * __ldg(oW + k * OUTC + j);
    out[idx] = acc;
}

// ---------------- launch ----------------------------------------------------
extern "C" void kernel_launch(void* const* d_in, const int* in_sizes, int n_in,
                              void* d_out, int out_size) {
    const float* xs  = (const float*)d_in[0];
    const int*   ei  = (const int*)  d_in[1];
    const float* Wz  = (const float*)d_in[2];
    const float* bz  = (const float*)d_in[3];
    const float* Wr  = (const float*)d_in[4];
    const float* br  = (const float*)d_in[5];
    const float* Wh  = (const float*)d_in[6];
    const float* bh  = (const float*)d_in[7];
    const float* Lz  = (const float*)d_in[8];
    const float* Lzb = (const float*)d_in[9];
    const float* Lr  = (const float*)d_in[10];
    const float* Lrb = (const float*)d_in[11];
    const float* Lh  = (const float*)d_in[12];
    const float* Lhb = (const float*)d_in[13];
    const float* oW  = (const float*)d_in[14];
    const float* ob  = (const float*)d_in[15];
    float* out = (float*)d_out;

    k_prep<<<3, 256>>>(Wz, bz, Wr, br, Wh, bh, Lz, Lzb, Lr, Lrb, Lh, Lhb);
    k_clear_h<<<(NN * HH + 255) / 256, 256>>>();
    k_clear_deg_all<<<(TT * NN + 255) / 256, 256>>>();

    k_deg_all<<<TT * DEG_BPS, 256>>>(ei);
    k_init_all<<<TT * INIT_BPS, 256>>>(xs);
    k_scatter_all<<<TT * SCAT_BPS, 256>>>(xs, ei);
    k_P<<<(TT * NN + 63) / 64, 256>>>();

    for (int t = 0; t < TT; t++)
        k_gates3<<<(NN + 63) / 64, 256>>>(t);

    k_out<<<(NN * OUTC + 255) / 256, 256>>>(oW, ob, out);
}

// round 5
// speedup vs baseline: 1.0405x; 1.0405x over previous
#include <cuda_runtime.h>
#include <math.h>

#define TT 6
#define NN 50000
#define EE 800000
#define FF 32
#define HH 64
#define OUTC 16
#define SPAD 68

#define TOTN (TT * NN)                 // 300000
#define SCAN_BLOCKS 1172               // ceil(TOTN/256)
#define AUX_PER_THREAD 5               // 256*5 = 1280 >= 1172
#define DEG_BPS   3125                 // EE/256
#define PLACE_BPS 3125
#define GATH_BPS  9375                 // TOTN*8/256

// ---------------- scratch (device globals; no allocation allowed) ----------
__device__ __align__(16) float g_aggx[(size_t)TT * NN * FF];  // A_hat@X, all steps
__device__ __align__(16) float g_h   [(size_t)NN * HH];
__device__ int   g_deg [TOTN];
__device__ int   g_roff[TOTN];          // exclusive row start (flattened, global)
__device__ int   g_cur [TOTN];          // placement cursors
__device__ int   g_bsum[SCAN_BLOCKS];   // per-block sums -> exclusive block offsets
__device__ int   g_csr [(size_t)TT * EE];  // src index per edge, grouped by (t,dst)
__device__ float g_dinv[TOTN];

// folded / transposed weights
__device__ __align__(16) float g_Mt [3][HH][FF];  // (W @ L_top)^T
__device__ __align__(16) float g_Lbt[3][HH][HH];  // L_bot^T
__device__ float g_bv[3][HH];

__device__ __forceinline__ float sigmoidf_(float x) {
    return 1.0f / (1.0f + __expf(-x));
}

// ---------------- prep / clears ---------------------------------------------

__global__ void k_clear_h() {
    unsigned idx = blockIdx.x * blockDim.x + threadIdx.x;
    if (idx < (unsigned)(NN * HH)) g_h[idx] = 0.0f;
}

__global__ void k_clear_int2() {   // clears g_deg and g_cur
    unsigned i = blockIdx.x * blockDim.x + threadIdx.x;
    if (i < (unsigned)TOTN) { g_deg[i] = 0; g_cur[i] = 0; }
}

// one block per gate: fold W@L_top, transpose L_bot, fold biases
__global__ void k_prep(const float* __restrict__ Wz, const float* __restrict__ bz,
                       const float* __restrict__ Wr, const float* __restrict__ br,
                       const float* __restrict__ Wh, const float* __restrict__ bh,
                       const float* __restrict__ Lz, const float* __restrict__ Lzb,
                       const float* __restrict__ Lr, const float* __restrict__ Lrb,
                       const float* __restrict__ Lh, const float* __restrict__ Lhb) {
    int g = blockIdx.x;
    int t = threadIdx.x;
    const float* W  = (g == 0) ? Wz  : (g == 1) ? Wr  : Wh;
    const float* b  = (g == 0) ? bz  : (g == 1) ? br  : bh;
    const float* L  = (g == 0) ? Lz  : (g == 1) ? Lr  : Lh;
    const float* Lb = (g == 0) ? Lzb : (g == 1) ? Lrb : Lhb;

    for (int e = t; e < HH * FF; e += 256) {
        int j = e >> 5, f = e & 31;
        float s = 0.f;
        #pragma unroll 8
        for (int m = 0; m < HH; m++) s += __ldg(W + f * HH + m) * __ldg(L + m * HH + j);
        g_Mt[g][j][f] = s;
    }
    for (int e = t; e < HH * HH; e += 256) {
        int j = e >> 6, k = e & 63;
        g_Lbt[g][j][k] = __ldg(L + (HH + k) * HH + j);
    }
    if (t < HH) {
        float sb = __ldg(Lb + t);
        #pragma unroll 8
        for (int m = 0; m < HH; m++) sb += __ldg(b + m) * __ldg(L + m * HH + t);
        g_bv[g][t] = sb;
    }
}

// ---------------- degree + dinv ----------------------------------------------

__global__ void k_deg_all(const int* __restrict__ ei) {
    int t = blockIdx.x / DEG_BPS;
    unsigned e = (blockIdx.x % DEG_BPS) * 256 + threadIdx.x;
    int d = __ldg(ei + (size_t)t * 2 * EE + EE + e);
    atomicAdd(&g_deg[t * NN + d], 1);
}

__global__ void k_dinv_all() {
    unsigned i = blockIdx.x * blockDim.x + threadIdx.x;
    if (i < (unsigned)TOTN) g_dinv[i] = rsqrtf((float)(g_deg[i] + 1));
}

// ---------------- exclusive scan of g_deg -> g_roff (3 kernels) -------------

__global__ void k_scan_block() {
    __shared__ int sh[256];
    int tid = threadIdx.x;
    int i = blockIdx.x * 256 + tid;
    int v = (i < TOTN) ? g_deg[i] : 0;
    sh[tid] = v;
    __syncthreads();
    #pragma unroll
    for (int off = 1; off < 256; off <<= 1) {
        int tv = (tid >= off) ? sh[tid - off] : 0;
        __syncthreads();
        sh[tid] += tv;
        __syncthreads();
    }
    if (i < TOTN) g_roff[i] = sh[tid] - v;         // exclusive within block
    if (tid == 255) g_bsum[blockIdx.x] = sh[255];  // block total
}

__global__ void k_scan_aux() {
    __shared__ int part[256];
    int tid = threadIdx.x;
    int start = tid * AUX_PER_THREAD;
    int loc[AUX_PER_THREAD];
    int vv [AUX_PER_THREAD];
    int sum = 0;
    #pragma unroll
    for (int j = 0; j < AUX_PER_THREAD; j++) {
        int idx = start + j;
        int v = (idx < SCAN_BLOCKS) ? g_bsum[idx] : 0;
        vv[j] = v;
        sum += v;
        loc[j] = sum;                               // inclusive within thread
    }
    part[tid] = sum;
    __syncthreads();
    #pragma unroll
    for (int off = 1; off < 256; off <<= 1) {
        int tv = (tid >= off) ? part[tid - off] : 0;
        __syncthreads();
        part[tid] += tv;
        __syncthreads();
    }
    int prev = (tid > 0) ? part[tid - 1] : 0;
    #pragma unroll
    for (int j = 0; j < AUX_PER_THREAD; j++) {
        int idx = start + j;
        if (idx < SCAN_BLOCKS) g_bsum[idx] = prev + loc[j] - vv[j];  // exclusive
    }
}

__global__ void k_scan_add() {
    int i = blockIdx.x * 256 + threadIdx.x;
    if (i < TOTN) g_roff[i] += g_bsum[blockIdx.x];
}

// ---------------- CSR placement ----------------------------------------------

__global__ void k_place(const int* __restrict__ ei) {
    int t = blockIdx.x / PLACE_BPS;
    unsigned e = (blockIdx.x % PLACE_BPS) * 256 + threadIdx.x;
    const int* base = ei + (size_t)t * 2 * EE;
    int s = __ldg(base + e);
    int d = __ldg(base + EE + e);
    int i = t * NN + d;
    int pos = g_roff[i] + atomicAdd(&g_cur[i], 1);
    g_csr[pos] = s;
}

// ---------------- pull-mode gather: aggx = A_hat @ X (incl. self loop) ------

__global__ void k_gather(const float* __restrict__ xs) {
    unsigned idx = blockIdx.x * 256 + threadIdx.x;   // < TOTN*8
    unsigned nf = idx >> 3;          // flat (t,node)
    unsigned c  = idx & 7u;
    int t = nf / NN;
    int node = nf - t * NN;
    const float* x = xs + (size_t)t * NN * FF;

    float dd = g_dinv[nf];
    float4 acc = __ldg(reinterpret_cast<const float4*>(x + (size_t)node * FF) + c);
    float d2 = dd * dd;
    acc.x *= d2; acc.y *= d2; acc.z *= d2; acc.w *= d2;

    int beg = g_roff[nf];
    int end = beg + g_deg[nf];
    const float* dinv_t = g_dinv + t * NN;
    for (int p = beg; p < end; p++) {
        int s = __ldg(g_csr + p);
        float ns = dd * __ldg(dinv_t + s);
        float4 v = __ldg(reinterpret_cast<const float4*>(x + (size_t)s * FF) + c);
        acc.x = fmaf(v.x, ns, acc.x);
        acc.y = fmaf(v.y, ns, acc.y);
        acc.z = fmaf(v.z, ns, acc.z);
        acc.w = fmaf(v.w, ns, acc.w);
    }
    reinterpret_cast<float4*>(g_aggx + (size_t)nf * FF)[c] = acc;
}

// ---------------- fused projection + GRU gates (per timestep) ---------------
__global__ void __launch_bounds__(256) k_gates2(int t) {
    __shared__ float ag_sh[FF][SPAD];
    __shared__ float h_sh [HH][SPAD];
    __shared__ float hr_sh[HH][SPAD];

    int tid = threadIdx.x;
    int block_base = blockIdx.x * 64;
    const float* aggx_t = g_aggx + (size_t)t * NN * FF;

    #pragma unroll
    for (int r = 0; r < 2; r++) {
        int idx = r * 256 + tid;
        int n = idx >> 3, k4 = idx & 7;
        int node = block_base + n;
        float4 v = make_float4(0.f, 0.f, 0.f, 0.f);
        if (node < NN) v = __ldg(reinterpret_cast<const float4*>(aggx_t + (size_t)node * FF) + k4);
        ag_sh[k4 * 4 + 0][n] = v.x;
        ag_sh[k4 * 4 + 1][n] = v.y;
        ag_sh[k4 * 4 + 2][n] = v.z;
        ag_sh[k4 * 4 + 3][n] = v.w;
    }
    #pragma unroll
    for (int r = 0; r < 4; r++) {
        int idx = r * 256 + tid;
        int n = idx >> 4, k4 = idx & 15;
        int node = block_base + n;
        float4 v = make_float4(0.f, 0.f, 0.f, 0.f);
        if (node < NN) v = __ldg(reinterpret_cast<const float4*>(g_h + (size_t)node * HH) + k4);
        h_sh[k4 * 4 + 0][n] = v.x;
        h_sh[k4 * 4 + 1][n] = v.y;
        h_sh[k4 * 4 + 2][n] = v.z;
        h_sh[k4 * 4 + 3][n] = v.w;
    }
    __syncthreads();

    int warp = tid >> 5, lane = tid & 31;
    int nb = warp * 8;
    int j0 = lane, j1 = lane + 32;

    float az0[8], az1[8], ar0[8], ar1[8];
    #pragma unroll
    for (int n = 0; n < 8; n++) { az0[n] = az1[n] = ar0[n] = ar1[n] = 0.f; }

    #pragma unroll
    for (int k4 = 0; k4 < FF / 4; k4++) {
        float4 wz0 = __ldg(reinterpret_cast<const float4*>(&g_Mt[0][j0][0]) + k4);
        float4 wz1 = __ldg(reinterpret_cast<const float4*>(&g_Mt[0][j1][0]) + k4);
        float4 wr0 = __ldg(reinterpret_cast<const float4*>(&g_Mt[1][j0][0]) + k4);
        float4 wr1 = __ldg(reinterpret_cast<const float4*>(&g_Mt[1][j1][0]) + k4);
        const float* pz0 = (const float*)&wz0; const float* pz1 = (const float*)&wz1;
        const float* pr0 = (const float*)&wr0; const float* pr1 = (const float*)&wr1;
        #pragma unroll
        for (int i = 0; i < 4; i++) {
            int k = k4 * 4 + i;
            float4 a0 = *reinterpret_cast<const float4*>(&ag_sh[k][nb]);
            float4 a1 = *reinterpret_cast<const float4*>(&ag_sh[k][nb + 4]);
            float aa[8] = {a0.x, a0.y, a0.z, a0.w, a1.x, a1.y, a1.z, a1.w};
            #pragma unroll
            for (int n = 0; n < 8; n++) {
                az0[n] = fmaf(aa[n], pz0[i], az0[n]);
                az1[n] = fmaf(aa[n], pz1[i], az1[n]);
                ar0[n] = fmaf(aa[n], pr0[i], ar0[n]);
                ar1[n] = fmaf(aa[n], pr1[i], ar1[n]);
            }
        }
    }
    #pragma unroll
    for (int k4 = 0; k4 < HH / 4; k4++) {
        float4 wz0 = __ldg(reinterpret_cast<const float4*>(&g_Lbt[0][j0][0]) + k4);
        float4 wz1 = __ldg(reinterpret_cast<const float4*>(&g_Lbt[0][j1][0]) + k4);
        float4 wr0 = __ldg(reinterpret_cast<const float4*>(&g_Lbt[1][j0][0]) + k4);
        float4 wr1 = __ldg(reinterpret_cast<const float4*>(&g_Lbt[1][j1][0]) + k4);
        const float* pz0 = (const float*)&wz0; const float* pz1 = (const float*)&wz1;
        const float* pr0 = (const float*)&wr0; const float* pr1 = (const float*)&wr1;
        #pragma unroll
        for (int i = 0; i < 4; i++) {
            int k = k4 * 4 + i;
            float4 a0 = *reinterpret_cast<const float4*>(&h_sh[k][nb]);
            float4 a1 = *reinterpret_cast<const float4*>(&h_sh[k][nb + 4]);
            float aa[8] = {a0.x, a0.y, a0.z, a0.w, a1.x, a1.y, a1.z, a1.w};
            #pragma unroll
            for (int n = 0; n < 8; n++) {
                az0[n] = fmaf(aa[n], pz0[i], az0[n]);
                az1[n] = fmaf(aa[n], pz1[i], az1[n]);
                ar0[n] = fmaf(aa[n], pr0[i], ar0[n]);
                ar1[n] = fmaf(aa[n], pr1[i], ar1[n]);
            }
        }
    }

    float bvz0 = __ldg(&g_bv[0][j0]), bvz1 = __ldg(&g_bv[0][j1]);
    float bvr0 = __ldg(&g_bv[1][j0]), bvr1 = __ldg(&g_bv[1][j1]);

    float Z0a[8], Z1a[8];
    #pragma unroll
    for (int n = 0; n < 8; n++) {
        Z0a[n] = sigmoidf_(az0[n] + bvz0);
        Z1a[n] = sigmoidf_(az1[n] + bvz1);
        float R0 = sigmoidf_(ar0[n] + bvr0);
        float R1 = sigmoidf_(ar1[n] + bvr1);
        hr_sh[j0][nb + n] = h_sh[j0][nb + n] * R0;
        hr_sh[j1][nb + n] = h_sh[j1][nb + n] * R1;
    }
    __syncwarp();

    float ah0[8], ah1[8];
    #pragma unroll
    for (int n = 0; n < 8; n++) { ah0[n] = ah1[n] = 0.f; }

    #pragma unroll
    for (int k4 = 0; k4 < FF / 4; k4++) {
        float4 wh0 = __ldg(reinterpret_cast<const float4*>(&g_Mt[2][j0][0]) + k4);
        float4 wh1 = __ldg(reinterpret_cast<const float4*>(&g_Mt[2][j1][0]) + k4);
        const float* p0 = (const float*)&wh0; const float* p1 = (const float*)&wh1;
        #pragma unroll
        for (int i = 0; i < 4; i++) {
            int k = k4 * 4 + i;
            float4 a0 = *reinterpret_cast<const float4*>(&ag_sh[k][nb]);
            float4 a1 = *reinterpret_cast<const float4*>(&ag_sh[k][nb + 4]);
            float aa[8] = {a0.x, a0.y, a0.z, a0.w, a1.x, a1.y, a1.z, a1.w};
            #pragma unroll
            for (int n = 0; n < 8; n++) {
                ah0[n] = fmaf(aa[n], p0[i], ah0[n]);
                ah1[n] = fmaf(aa[n], p1[i], ah1[n]);
            }
        }
    }
    #pragma unroll
    for (int k4 = 0; k4 < HH / 4; k4++) {
        float4 wh0 = __ldg(reinterpret_cast<const float4*>(&g_Lbt[2][j0][0]) + k4);
        float4 wh1 = __ldg(reinterpret_cast<const float4*>(&g_Lbt[2][j1][0]) + k4);
        const float* p0 = (const float*)&wh0; const float* p1 = (const float*)&wh1;
        #pragma unroll
        for (int i = 0; i < 4; i++) {
            int k = k4 * 4 + i;
            float4 a0 = *reinterpret_cast<const float4*>(&hr_sh[k][nb]);
            float4 a1 = *reinterpret_cast<const float4*>(&hr_sh[k][nb + 4]);
            float aa[8] = {a0.x, a0.y, a0.z, a0.w, a1.x, a1.y, a1.z, a1.w};
            #pragma unroll
            for (int n = 0; n < 8; n++) {
                ah0[n] = fmaf(aa[n], p0[i], ah0[n]);
                ah1[n] = fmaf(aa[n], p1[i], ah1[n]);
            }
        }
    }

    float bvh0 = __ldg(&g_bv[2][j0]), bvh1 = __ldg(&g_bv[2][j1]);
    #pragma unroll
    for (int n = 0; n < 8; n++) {
        int node = block_base + nb + n;
        if (node < NN) {
            float Ht0 = tanhf(ah0[n] + bvh0);
            float Ht1 = tanhf(ah1[n] + bvh1);
            float h0 = h_sh[j0][nb + n];
            float h1 = h_sh[j1][nb + n];
            g_h[(size_t)node * HH + j0] = Z0a[n] * h0 + (1.f - Z0a[n]) * Ht0;
            g_h[(size_t)node * HH + j1] = Z1a[n] * h1 + (1.f - Z1a[n]) * Ht1;
        }
    }
}

__global__ void k_out(const float* __restrict__ oW, const float* __restrict__ ob,
                      float* __restrict__ out) {
    unsigned idx = blockIdx.x * blockDim.x + threadIdx.x;
    if (idx >= (unsigned)(NN * OUTC)) return;
    int i = idx >> 4, j = idx & 15;
    const float* hr = g_h + (size_t)i * HH;
    float acc = __ldg(ob + j);
    #pragma unroll
    for (int k = 0; k < HH; k++) acc += hr[k] * __ldg(oW + k * OUTC + j);
    out[idx] = acc;
}

// ---------------- launch ----------------------------------------------------
extern "C" void kernel_launch(void* const* d_in, const int* in_sizes, int n_in,
                              void* d_out, int out_size) {
    const float* xs  = (const float*)d_in[0];
    const int*   ei  = (const int*)  d_in[1];
    const float* Wz  = (const float*)d_in[2];
    const float* bz  = (const float*)d_in[3];
    const float* Wr  = (const float*)d_in[4];
    const float* br  = (const float*)d_in[5];
    const float* Wh  = (const float*)d_in[6];
    const float* bh  = (const float*)d_in[7];
    const float* Lz  = (const float*)d_in[8];
    const float* Lzb = (const float*)d_in[9];
    const float* Lr  = (const float*)d_in[10];
    const float* Lrb = (const float*)d_in[11];
    const float* Lh  = (const float*)d_in[12];
    const float* Lhb = (const float*)d_in[13];
    const float* oW  = (const float*)d_in[14];
    const float* ob  = (const float*)d_in[15];
    float* out = (float*)d_out;

    k_prep<<<3, 256>>>(Wz, bz, Wr, br, Wh, bh, Lz, Lzb, Lr, Lrb, Lh, Lhb);
    k_clear_h<<<(NN * HH + 255) / 256, 256>>>();
    k_clear_int2<<<SCAN_BLOCKS, 256>>>();

    k_deg_all<<<TT * DEG_BPS, 256>>>(ei);
    k_dinv_all<<<SCAN_BLOCKS, 256>>>();
    k_scan_block<<<SCAN_BLOCKS, 256>>>();
    k_scan_aux<<<1, 256>>>();
    k_scan_add<<<SCAN_BLOCKS, 256>>>();
    k_place<<<TT * PLACE_BPS, 256>>>(ei);
    k_gather<<<GATH_BPS, 256>>>(xs);

    for (int t = 0; t < TT; t++)
        k_gates2<<<(NN + 63) / 64, 256>>>(t);

    k_out<<<(NN * OUTC + 255) / 256, 256>>>(oW, ob, out);
}